// round 2
// baseline (speedup 1.0000x reference)
#include <cuda_runtime.h>
#include <cstdint>

// CostVolumeLayer3D, B=2 C=64 D=32 H=64 W=64, R=2.
// out[b, ch(s,dsh), d, h, w] = (1/125) * sum_c x1[b,c,d,h,w] * x2[b,c,d-dsh,h-i_s,w-j_s]
//   with s in [-4,4], dsh in [-2,2], (i_s,j_s) = (min(2,s+2), max(-2,s-2)),
//   ch = (5s+dsh) mod 125.  Channels 23..102 are identically zero.

#define LD64(p) (*reinterpret_cast<const unsigned long long*>(p))

static __device__ __forceinline__ void cp16(uint32_t dst, const float* src, int vsz) {
    asm volatile("cp.async.cg.shared.global [%0], [%1], 16, %2;"
                 :: "r"(dst), "l"(src), "r"(vsz));
}
static __device__ __forceinline__ unsigned long long pk2(uint32_t lo, uint32_t hi) {
    unsigned long long r;
    asm("mov.b64 %0, {%1,%2};" : "=l"(r) : "r"(lo), "r"(hi));
    return r;
}
static __device__ __forceinline__ void unpk(uint32_t& lo, uint32_t& hi, unsigned long long v) {
    asm("mov.b64 {%0,%1}, %2;" : "=r"(lo), "=r"(hi) : "l"(v));
}
static __device__ __forceinline__ void fma2(unsigned long long& acc,
                                            unsigned long long a, unsigned long long b) {
    asm("fma.rn.f32x2 %0, %1, %2, %0;" : "+l"(acc) : "l"(a), "l"(b));
}
static __device__ __forceinline__ unsigned long long mul2(unsigned long long a,
                                                          unsigned long long b) {
    unsigned long long r;
    asm("mul.rn.f32x2 %0, %1, %2;" : "=l"(r) : "l"(a), "l"(b));
    return r;
}

// Shared layout (floats), double buffered (BUF = 6208 floats = 24832 B):
//   x2: 6 planes * (12 rows * 72 cols); smem col = global_w + 4 (W halo at cols 2,3,68,69)
//   x1 at +5184: 2 planes * (8 rows * 64 cols)
extern __shared__ float sm[];

__global__ void __launch_bounds__(256, 1)
cv3d_kernel(const float* __restrict__ x1, const float* __restrict__ x2,
            float* __restrict__ out)
{
    const int tid = threadIdx.x;
    const int hl  = tid >> 5;           // h row in tile (warp = one row)
    const int w   = (tid & 31) * 2;     // even w; thread owns (w, w+1)
    const int h0  = blockIdx.x * 8;
    const int d0  = blockIdx.y * 2;
    const int b   = blockIdx.z;

    const float* x1b = x1 + (size_t)b * 8388608;
    const float* x2b = x2 + (size_t)b * 8388608;
    const uint32_t smb = (uint32_t)__cvta_generic_to_shared(sm);

    // ---- cp.async chunk table (channel-invariant): 1152 x2 + 256 x1 = 1408 chunks ----
    const float* csrc[6]; uint32_t cdst[6]; int cvsz[6]; bool cact[6];
    #pragma unroll
    for (int k = 0; k < 6; ++k) {
        int q = tid + k * 256;
        cact[k] = (q < 1408);
        const float* s; uint32_t doff; int v;
        if (q < 1152) {                       // x2: plane, 12 rows, 16x16B chunks
            int pl = q / 192, r = q % 192, row = r >> 4, cw = r & 15;
            int gd = d0 - 2 + pl, gh = h0 - 2 + row;
            bool inr = ((unsigned)gd < 32u) && ((unsigned)gh < 64u);
            v = inr ? 16 : 0;                 // src-size 0 => zero-fill (D/H halo)
            s = x2b + (size_t)(inr ? gd : 0) * 4096 + (inr ? gh : 0) * 64 + cw * 4;
            doff = (uint32_t)(pl * 864 + row * 72 + 4 + cw * 4);
        } else {                              // x1: 2 planes, 8 rows, 16x16B chunks
            int t = q - 1152;
            int a = (t >> 7) & 1, row = (t >> 4) & 7, cw = t & 15;
            v = 16;
            s = x1b + (size_t)(d0 + a) * 4096 + (h0 + row) * 64 + cw * 4;
            doff = (uint32_t)(5184 + a * 512 + row * 64 + cw * 4);
        }
        csrc[k] = s; cdst[k] = smb + doff * 4u; cvsz[k] = v;
    }

    // ---- prefetch channel 0 into buffer 0 ----
    #pragma unroll
    for (int k = 0; k < 6; ++k)
        if (cact[k]) cp16(cdst[k], csrc[k], cvsz[k]);
    asm volatile("cp.async.commit_group;");

    // ---- zero the W-halo columns of both buffers (image edge => always 0) ----
    if (tid < 144) {
        int buf = tid / 72, r = tid % 72, pl = r / 12, row = r % 12;
        float* hp = sm + buf * 6208 + pl * 864 + row * 72;
        hp[2] = 0.f; hp[3] = 0.f; hp[68] = 0.f; hp[69] = 0.f;
    }

    // ---- zero the 80 never-written output channels (23..102) for this tile ----
    {
        float* zb = out + (size_t)b * 16384000 + (size_t)23 * 131072
                        + (size_t)d0 * 4096 + h0 * 64;
        int dd = (tid >> 7) & 1, row = (tid >> 4) & 7, cw = tid & 15;
        float* base = zb + dd * 4096 + row * 64 + cw * 4;
        const float4 z = make_float4(0.f, 0.f, 0.f, 0.f);
        #pragma unroll 8
        for (int ch = 0; ch < 80; ++ch)
            *reinterpret_cast<float4*>(base + (size_t)ch * 131072) = z;
    }

    // ---- accumulators: [d-index][dsh+2][s+4], f32x2 lanes = (w, w+1) ----
    unsigned long long acc[2][5][9];
    #pragma unroll
    for (int a = 0; a < 2; ++a)
        #pragma unroll
        for (int u = 0; u < 5; ++u)
            #pragma unroll
            for (int v = 0; v < 9; ++v) acc[a][u][v] = 0ull;

    #pragma unroll 1
    for (int c = 0; c < 64; ++c) {
        const int P = c & 1;
        if (c < 63) {
            #pragma unroll
            for (int k = 0; k < 6; ++k)
                if (cact[k]) cp16(cdst[k] + (uint32_t)((P ^ 1) * 24832),
                                  csrc[k] + (size_t)(c + 1) * 131072, cvsz[k]);
            asm volatile("cp.async.commit_group;");
            asm volatile("cp.async.wait_group 1;");
        } else {
            asm volatile("cp.async.wait_group 0;");
        }
        __syncthreads();

        const float* xw = sm + P * 6208 + hl * 72 + (w + 4);   // plane row hh-2, col ww
        const float* ax = sm + P * 6208 + 5184 + hl * 64 + w;
        const unsigned long long A0 = LD64(ax);                // x1 (d0,  hh, w..w+1)
        const unsigned long long A1 = LD64(ax + 512);          // x1 (d0+1,hh, w..w+1)

        #pragma unroll
        for (int p = 0; p < 6; ++p) {                          // x2 plane gd = d0-2+p
            const float* pb = xw + p * 864;
            unsigned long long f0 = LD64(pb - 2);    // row hh-2: cols ww-2,ww-1
            unsigned long long f2 = LD64(pb);        //            cols ww,  ww+1
            unsigned long long f4 = LD64(pb + 2);    //            cols ww+2,ww+3
            unsigned long long l1 = LD64(pb + 74);   // row hh-1, cols ww+2,ww+3
            unsigned long long l2 = LD64(pb + 146);  // row hh
            unsigned long long l3 = LD64(pb + 218);  // row hh+1
            unsigned long long l4 = LD64(pb + 290);  // row hh+2
            uint32_t f0lo, f0hi, f2lo, f2hi, f4lo, f4hi;
            unpk(f0lo, f0hi, f0); unpk(f2lo, f2hi, f2); unpk(f4lo, f4hi, f4);
            unsigned long long bb[9];
            bb[0] = l4;                 // s=-4: (hh+2, ww+2)
            bb[1] = l3;                 // s=-3
            bb[2] = l2;                 // s=-2
            bb[3] = l1;                 // s=-1
            bb[4] = f4;                 // s= 0: (hh-2, ww+2)
            bb[5] = pk2(f2hi, f4lo);    // s= 1: (hh-2, ww+1)
            bb[6] = f2;                 // s= 2: (hh-2, ww)
            bb[7] = pk2(f0hi, f2lo);    // s= 3: (hh-2, ww-1)
            bb[8] = f0;                 // s= 4: (hh-2, ww-2)
            if (p <= 4) {               // voxel d0:   dsh = 2-p -> u = 4-p
                #pragma unroll
                for (int v = 0; v < 9; ++v) fma2(acc[0][4 - p][v], A0, bb[v]);
            }
            if (p >= 1) {               // voxel d0+1: dsh = 3-p -> u = 5-p
                #pragma unroll
                for (int v = 0; v < 9; ++v) fma2(acc[1][5 - p][v], A1, bb[v]);
            }
        }
        __syncthreads();
    }

    // ---- epilogue: scale by 1/125 and store ----
    const uint32_t invb = __float_as_uint(1.0f / 125.0f);
    const unsigned long long invv = pk2(invb, invb);
    float* ob = out + (size_t)b * 16384000 + (size_t)d0 * 4096
                    + (size_t)(h0 + hl) * 64 + w;
    #pragma unroll
    for (int a = 0; a < 2; ++a)
        #pragma unroll
        for (int u = 0; u < 5; ++u)
            #pragma unroll
            for (int v = 0; v < 9; ++v) {
                int ch = (5 * (v - 4) + (u - 2)) % 125;
                if (ch < 0) ch += 125;
                unsigned long long r = mul2(acc[a][u][v], invv);
                *reinterpret_cast<unsigned long long*>(
                    ob + (size_t)ch * 131072 + a * 4096) = r;
            }
}

extern "C" void kernel_launch(void* const* d_in, const int* in_sizes, int n_in,
                              void* d_out, int out_size) {
    const float* x1 = (const float*)d_in[0];
    const float* x2 = (const float*)d_in[1];
    float* out = (float*)d_out;
    cudaFuncSetAttribute(cv3d_kernel,
                         cudaFuncAttributeMaxDynamicSharedMemorySize, 49664);
    cv3d_kernel<<<dim3(8, 16, 2), 256, 49664>>>(x1, x2, out);
}

// round 3
// speedup vs baseline: 1.0788x; 1.0788x over previous
#include <cuda_runtime.h>
#include <cstdint>

// CostVolumeLayer3D, B=2 C=64 D=32 H=64 W=64, R=2.
// out[b, ch(s,dsh), d, h, w] = (1/125) * sum_c x1[b,c,d,h,w] * x2[b,c,d-dsh,h-i_s,w-j_s]
//   s in [-4,4], dsh in [-2,2], (i_s,j_s) = (min(2,s+2), max(-2,s-2)),
//   ch = (5s+dsh) mod 125. Channels 23..102 are identically zero.
// Thread = (w-pair) x (d-pair): 4 voxels, 90 f32x2 accumulators.
// 128-thread CTA (4 h-rows), 2 CTAs/SM, 3-stage cp.async pipeline, 1 barrier/channel.

#define LD64(p) (*reinterpret_cast<const unsigned long long*>(p))

static __device__ __forceinline__ void cp16(uint32_t dst, const float* src, int vsz) {
    asm volatile("cp.async.cg.shared.global [%0], [%1], 16, %2;"
                 :: "r"(dst), "l"(src), "r"(vsz));
}
static __device__ __forceinline__ unsigned long long pk2(uint32_t lo, uint32_t hi) {
    unsigned long long r;
    asm("mov.b64 %0, {%1,%2};" : "=l"(r) : "r"(lo), "r"(hi));
    return r;
}
static __device__ __forceinline__ void unpk(uint32_t& lo, uint32_t& hi, unsigned long long v) {
    asm("mov.b64 {%0,%1}, %2;" : "=r"(lo), "=r"(hi) : "l"(v));
}
static __device__ __forceinline__ void fma2(unsigned long long& acc,
                                            unsigned long long a, unsigned long long b) {
    asm("fma.rn.f32x2 %0, %1, %2, %0;" : "+l"(acc) : "l"(a), "l"(b));
}
static __device__ __forceinline__ unsigned long long mul2(unsigned long long a,
                                                          unsigned long long b) {
    unsigned long long r;
    asm("mul.rn.f32x2 %0, %1, %2;" : "=l"(r) : "l"(a), "l"(b));
    return r;
}

// Per-buffer smem layout (floats), 3 buffers (BUF = 3968 floats = 15872 B):
//   x2: 6 planes * (8 rows * 72 cols); smem col = global_w + 4 (W halo cols 2,3,68,69)
//   x1 at +3456: 2 planes * (4 rows * 64 cols)
extern __shared__ float sm[];

__global__ void __launch_bounds__(128, 2)
cv3d_kernel(const float* __restrict__ x1, const float* __restrict__ x2,
            float* __restrict__ out)
{
    const int tid = threadIdx.x;
    const int hl  = tid >> 5;           // 0..3: h row within tile (warp = one row)
    const int w   = (tid & 31) * 2;     // even w; thread owns (w, w+1)
    const int h0  = blockIdx.x * 4;
    const int d0  = blockIdx.y * 2;
    const int b   = blockIdx.z;

    const float* x1b = x1 + (size_t)b * 8388608;
    const float* x2b = x2 + (size_t)b * 8388608;
    const uint32_t smb = (uint32_t)__cvta_generic_to_shared(sm);

    // ---- cp.async chunk table (channel-invariant): 768 x2 + 128 x1 = 896 = 7*128 ----
    const float* csrc[7]; uint32_t cdst[7]; int cvsz[7];
    #pragma unroll
    for (int k = 0; k < 7; ++k) {
        int q = tid + k * 128;
        const float* s; uint32_t doff; int v;
        if (q < 768) {                        // x2: 6 planes, 8 rows, 16x16B chunks
            int pl = q >> 7, r = q & 127, row = r >> 4, cw = r & 15;
            int gd = d0 - 2 + pl, gh = h0 - 2 + row;
            bool inr = ((unsigned)gd < 32u) && ((unsigned)gh < 64u);
            v = inr ? 16 : 0;                 // src-size 0 => zero-fill (D/H halo)
            s = x2b + (size_t)(inr ? gd : 0) * 4096 + (inr ? gh : 0) * 64 + cw * 4;
            doff = (uint32_t)(pl * 576 + row * 72 + 4 + cw * 4);
        } else {                              // x1: 2 planes, 4 rows, 16x16B chunks
            int t = q - 768;
            int a = (t >> 6) & 1, row = (t >> 4) & 3, cw = t & 15;
            v = 16;
            s = x1b + (size_t)(d0 + a) * 4096 + (size_t)(h0 + row) * 64 + cw * 4;
            doff = (uint32_t)(3456 + a * 256 + row * 64 + cw * 4);
        }
        csrc[k] = s; cdst[k] = smb + doff * 4u; cvsz[k] = v;
    }

    // ---- prologue: prefetch channels 0 and 1 into buffers 0 and 1 ----
    #pragma unroll
    for (int k = 0; k < 7; ++k) cp16(cdst[k], csrc[k], cvsz[k]);
    asm volatile("cp.async.commit_group;");
    #pragma unroll
    for (int k = 0; k < 7; ++k) cp16(cdst[k] + 15872u, csrc[k] + 131072, cvsz[k]);
    asm volatile("cp.async.commit_group;");
    #pragma unroll
    for (int k = 0; k < 7; ++k) csrc[k] += 2 * 131072;   // now point at channel 2

    // ---- zero W-halo columns of all 3 buffers (image edge => always 0) ----
    for (int q = tid; q < 144; q += 128) {
        int buf = q / 48, r = q % 48, pl = r >> 3, row = r & 7;
        float* hp = sm + buf * 3968 + pl * 576 + row * 72;
        hp[2] = 0.f; hp[3] = 0.f; hp[68] = 0.f; hp[69] = 0.f;
    }

    // ---- zero the 80 never-written output channels (23..102) for this tile ----
    {
        float* zb = out + (size_t)b * 16384000 + (size_t)23 * 131072
                        + (size_t)d0 * 4096 + (size_t)h0 * 64;
        int dd = (tid >> 6) & 1, row = (tid >> 4) & 3, cw = tid & 15;
        float* base = zb + dd * 4096 + row * 64 + cw * 4;
        const float4 z = make_float4(0.f, 0.f, 0.f, 0.f);
        #pragma unroll 4
        for (int ch = 0; ch < 80; ++ch)
            *reinterpret_cast<float4*>(base + (size_t)ch * 131072) = z;
    }

    // ---- accumulators: [d-index][dsh+2][s+4], f32x2 lanes = (w, w+1) ----
    unsigned long long acc[2][5][9];
    #pragma unroll
    for (int a = 0; a < 2; ++a)
        #pragma unroll
        for (int u = 0; u < 5; ++u)
            #pragma unroll
            for (int v = 0; v < 9; ++v) acc[a][u][v] = 0ull;

    int cbuf = 0;   // buffer holding channel c (bytes offset = cbuf*15872)
    int pbuf = 2;   // buffer to prefetch channel c+2 into

    #pragma unroll 1
    for (int c = 0; c < 64; ++c) {
        if (c < 63) asm volatile("cp.async.wait_group 1;");
        else        asm volatile("cp.async.wait_group 0;");
        __syncthreads();

        if (c < 62) {
            const uint32_t po = (uint32_t)pbuf * 15872u;
            #pragma unroll
            for (int k = 0; k < 7; ++k) {
                cp16(cdst[k] + po, csrc[k], cvsz[k]);
                csrc[k] += 131072;
            }
            asm volatile("cp.async.commit_group;");
        }

        const float* base = sm + cbuf * 3968;
        const float* xw = base + hl * 72 + (w + 4);     // row (gh-2), col ww
        const float* ax = base + 3456 + hl * 64 + w;
        const unsigned long long A0 = LD64(ax);         // x1 (d0,   gh, w..w+1)
        const unsigned long long A1 = LD64(ax + 256);   // x1 (d0+1, gh, w..w+1)

        #pragma unroll
        for (int p = 0; p < 6; ++p) {                   // x2 plane gd = d0-2+p
            const float* pb = xw + p * 576;
            unsigned long long f0 = LD64(pb - 2);   // row gh-2: cols ww-2,ww-1
            unsigned long long f2 = LD64(pb);       //            cols ww,  ww+1
            unsigned long long f4 = LD64(pb + 2);   //            cols ww+2,ww+3
            unsigned long long l1 = LD64(pb + 74);  // row gh-1, cols ww+2,ww+3
            unsigned long long l2 = LD64(pb + 146); // row gh
            unsigned long long l3 = LD64(pb + 218); // row gh+1
            unsigned long long l4 = LD64(pb + 290); // row gh+2
            uint32_t f0lo, f0hi, f2lo, f2hi, f4lo, f4hi;
            unpk(f0lo, f0hi, f0); unpk(f2lo, f2hi, f2); unpk(f4lo, f4hi, f4);
            unsigned long long bb[9];
            bb[0] = l4;                 // s=-4: (gh+2, ww+2)
            bb[1] = l3;                 // s=-3
            bb[2] = l2;                 // s=-2
            bb[3] = l1;                 // s=-1
            bb[4] = f4;                 // s= 0: (gh-2, ww+2)
            bb[5] = pk2(f2hi, f4lo);    // s= 1: (gh-2, ww+1)
            bb[6] = f2;                 // s= 2: (gh-2, ww)
            bb[7] = pk2(f0hi, f2lo);    // s= 3: (gh-2, ww-1)
            bb[8] = f0;                 // s= 4: (gh-2, ww-2)
            if (p <= 4) {               // voxel d0:   dsh = 2-p -> u = 4-p
                #pragma unroll
                for (int v = 0; v < 9; ++v) fma2(acc[0][4 - p][v], A0, bb[v]);
            }
            if (p >= 1) {               // voxel d0+1: dsh = 3-p -> u = 5-p
                #pragma unroll
                for (int v = 0; v < 9; ++v) fma2(acc[1][5 - p][v], A1, bb[v]);
            }
        }

        cbuf = (cbuf == 2) ? 0 : cbuf + 1;
        pbuf = (pbuf == 2) ? 0 : pbuf + 1;
    }

    // ---- epilogue: scale by 1/125 and store ----
    const uint32_t invb = __float_as_uint(1.0f / 125.0f);
    const unsigned long long invv = pk2(invb, invb);
    float* ob = out + (size_t)b * 16384000 + (size_t)d0 * 4096
                    + (size_t)(h0 + hl) * 64 + w;
    #pragma unroll
    for (int a = 0; a < 2; ++a)
        #pragma unroll
        for (int u = 0; u < 5; ++u)
            #pragma unroll
            for (int v = 0; v < 9; ++v) {
                int ch = (5 * (v - 4) + (u - 2)) % 125;
                if (ch < 0) ch += 125;
                unsigned long long r = mul2(acc[a][u][v], invv);
                *reinterpret_cast<unsigned long long*>(
                    ob + (size_t)ch * 131072 + a * 4096) = r;
            }
}

extern "C" void kernel_launch(void* const* d_in, const int* in_sizes, int n_in,
                              void* d_out, int out_size) {
    const float* x1 = (const float*)d_in[0];
    const float* x2 = (const float*)d_in[1];
    float* out = (float*)d_out;
    cudaFuncSetAttribute(cv3d_kernel,
                         cudaFuncAttributeMaxDynamicSharedMemorySize, 47616);
    cv3d_kernel<<<dim3(16, 16, 2), 128, 47616>>>(x1, x2, out);
}